// round 9
// baseline (speedup 1.0000x reference)
#include <cuda_runtime.h>
#include <cstdint>

#define BATCH 8
#define CH    512
#define PIX   4096            // 64*64
#define CP    (CH*PIX)        // 2,097,152
#define TOT   (BATCH*CP)      // 16,777,216

// Scratch (device globals: allocation-free per harness rules)
__device__ float  g_f[2][TOT];      // conv outputs f_opt / f_sar
__device__ float  g_S[2][TOT];      // Gram matrices S_opt / S_sar
__device__ float4 g_red[BATCH*PIX]; // per-(b,pixel): (m1, z1, m2, z2)

// Packed f32x2 FMA: d = a*b + c elementwise on two packed fp32 lanes.
// Baseline sm_100-family PTX (not an 'a'-feature) — ptxas never emits it
// from C++ so it must come from inline PTX.
__device__ __forceinline__ double ffma2(double a, double b, double c) {
    double d;
    asm("fma.rn.f32x2 %0, %1, %2, %3;" : "=d"(d) : "d"(a), "d"(b), "d"(c));
    return d;
}
__device__ __forceinline__ float lo32(double d) { return __int_as_float(__double2loint(d)); }
__device__ __forceinline__ float hi32(double d) { return __int_as_float(__double2hiint(d)); }

// ---------------------------------------------------------------------------
// Kernel A: 1x1 conv as SGEMM.  F[b][o][p] = sum_c W[o][c] * X[b][c][p]
// M=512 (o), N=4096 (p), K=512 (c); 16 GEMMs (8 batches x 2 branches).
// 128x128 block tile, BK=8, 8x8 per thread, 256 threads, double-buffered smem.
// A tile stored DUPLICATED (x,x,y,y,...) so LDS.128 yields packed (a,a)
// doubles directly; inner product runs on fma.rn.f32x2 (2 FMA/instr).
// ---------------------------------------------------------------------------
__global__ __launch_bounds__(256, 2)
void conv_gemm(const float* __restrict__ opt, const float* __restrict__ sar,
               const float* __restrict__ Wopt, const float* __restrict__ Wsar)
{
    const int branch = blockIdx.z >> 3;
    const int batch  = blockIdx.z & 7;
    const float* __restrict__ Wm = branch ? Wsar : Wopt;
    const float* __restrict__ X  = (branch ? sar : opt) + (size_t)batch * CP;
    float* __restrict__ F = g_f[branch] + (size_t)batch * CP;

    __shared__ float As[2][8][256];   // [k][2*m] duplicated pairs
    __shared__ float Bs[2][8][128];   // [k][n]

    const int t      = threadIdx.x;
    const int m_base = blockIdx.y * 128;
    const int n_base = blockIdx.x * 128;

    // loader coordinates
    const int arow = t >> 1;           // 0..127  (m within tile)
    const int acol = (t & 1) * 4;      // 0 or 4  (k within tile)
    const int brow = t >> 5;           // 0..7    (k within tile)
    const int bcol = (t & 31) * 4;     // 0..124  (n within tile)

    const float* Aptr = Wm + (size_t)(m_base + arow) * CH + acol;
    const float* Bptr = X  + (size_t)brow * PIX + n_base + bcol;

    // compute coordinates
    const int m0 = (t >> 4) * 8;
    const int n0 = (t & 15) * 8;

    double acc[8][4];                  // packed: acc[i][j] = (out[i][2j], out[i][2j+1])
    #pragma unroll
    for (int i = 0; i < 8; i++)
        #pragma unroll
        for (int j = 0; j < 4; j++) acc[i][j] = 0.0;

    // preload k-tile 0
    {
        float4 a = *(const float4*)(Aptr);
        float4 b = *(const float4*)(Bptr);
        const float av[4] = {a.x, a.y, a.z, a.w};
        #pragma unroll
        for (int q = 0; q < 4; q++)
            *(float2*)&As[0][acol + q][2 * arow] = make_float2(av[q], av[q]);
        *(float4*)&Bs[0][brow][bcol] = b;
    }
    __syncthreads();

    for (int kt = 0; kt < 64; ++kt) {
        const int buf = kt & 1;
        float4 an, bn;
        if (kt < 63) {
            an = *(const float4*)(Aptr + (kt + 1) * 8);
            bn = *(const float4*)(Bptr + (size_t)(kt + 1) * 8 * PIX);
        }
        #pragma unroll
        for (int k = 0; k < 8; ++k) {
            const double2* ad = (const double2*)&As[buf][k][2 * m0];
            const double2* bd = (const double2*)&Bs[buf][k][n0];
            double2 A0 = ad[0], A1 = ad[1], A2 = ad[2], A3 = ad[3];
            double2 B0 = bd[0], B1 = bd[1];
            double pa[8] = {A0.x, A0.y, A1.x, A1.y, A2.x, A2.y, A3.x, A3.y};
            double pb[4] = {B0.x, B0.y, B1.x, B1.y};
            #pragma unroll
            for (int i = 0; i < 8; i++)
                #pragma unroll
                for (int j = 0; j < 4; j++)
                    acc[i][j] = ffma2(pa[i], pb[j], acc[i][j]);
        }
        if (kt < 63) {
            const int nb = buf ^ 1;
            const float av[4] = {an.x, an.y, an.z, an.w};
            #pragma unroll
            for (int q = 0; q < 4; q++)
                *(float2*)&As[nb][acol + q][2 * arow] = make_float2(av[q], av[q]);
            *(float4*)&Bs[nb][brow][bcol] = bn;
            __syncthreads();
        }
    }

    #pragma unroll
    for (int i = 0; i < 8; i++) {
        float* o = F + (size_t)(m_base + m0 + i) * PIX + n_base + n0;
        *(float4*)(o)     = make_float4(lo32(acc[i][0]), hi32(acc[i][0]),
                                        lo32(acc[i][1]), hi32(acc[i][1]));
        *(float4*)(o + 4) = make_float4(lo32(acc[i][2]), hi32(acc[i][2]),
                                        lo32(acc[i][3]), hi32(acc[i][3]));
    }
}

// ---------------------------------------------------------------------------
// Kernel B: per-(b,c) Gram matrix S = f^T f (64x64x64), both branches per CTA.
// 128 threads: threads [0,64) -> branch 0, [64,128) -> branch 1.
// Each thread computes an 8x8 output tile via fma.rn.f32x2.
// Dynamic smem: sh[2][64][64] (b-side) + shd[2][64][128] (duplicated a-side).
// ---------------------------------------------------------------------------
#define ATTN_SMEM (2*64*64*4 + 2*64*128*4)   // 98304 bytes

__global__ __launch_bounds__(128)
void attn_gemm()
{
    extern __shared__ float ash[];
    float* sh  = ash;                 // [br][h][j]   : br*4096 + h*64 + j
    float* shd = ash + 2 * 64 * 64;   // [br][h][2i]  : br*8192 + h*128 + 2i

    const int bc = blockIdx.x;                   // 0..4095 = b*512+c
    const int t = threadIdx.x;

    // cooperative load: 2 * 4096 floats; write linear + duplicated copies
    {
        const float4* g0 = (const float4*)(g_f[0] + (size_t)bc * PIX);
        const float4* g1 = (const float4*)(g_f[1] + (size_t)bc * PIX);
        #pragma unroll
        for (int i = 0; i < 8; i++) {
            int idx = t + 128 * i;                // float4 index within branch
            int h  = idx >> 4;
            int c4 = (idx & 15) * 4;
            float4 v0 = g0[idx];
            float4 v1 = g1[idx];
            *(float4*)&sh[h * 64 + c4]        = v0;
            *(float4*)&sh[4096 + h * 64 + c4] = v1;
            float* d0 = &shd[h * 128 + 2 * c4];
            float* d1 = &shd[8192 + h * 128 + 2 * c4];
            *(float2*)(d0)     = make_float2(v0.x, v0.x);
            *(float2*)(d0 + 2) = make_float2(v0.y, v0.y);
            *(float2*)(d0 + 4) = make_float2(v0.z, v0.z);
            *(float2*)(d0 + 6) = make_float2(v0.w, v0.w);
            *(float2*)(d1)     = make_float2(v1.x, v1.x);
            *(float2*)(d1 + 2) = make_float2(v1.y, v1.y);
            *(float2*)(d1 + 4) = make_float2(v1.z, v1.z);
            *(float2*)(d1 + 6) = make_float2(v1.w, v1.w);
        }
    }
    __syncthreads();

    const int branch = t >> 6;
    const int tt = t & 63;
    const int i0 = (tt >> 3) * 8;
    const int j0 = (tt & 7) * 8;

    const float* shb  = sh  + branch * 4096;
    const float* shdb = shd + branch * 8192;

    double acc[8][4];
    #pragma unroll
    for (int i = 0; i < 8; i++)
        #pragma unroll
        for (int j = 0; j < 4; j++) acc[i][j] = 0.0;

    for (int h = 0; h < 64; ++h) {
        const double2* ad = (const double2*)&shdb[h * 128 + 2 * i0];
        const double2* bd = (const double2*)&shb[h * 64 + j0];
        double2 A0 = ad[0], A1 = ad[1], A2 = ad[2], A3 = ad[3];
        double2 B0 = bd[0], B1 = bd[1];
        double pa[8] = {A0.x, A0.y, A1.x, A1.y, A2.x, A2.y, A3.x, A3.y};
        double pb[4] = {B0.x, B0.y, B1.x, B1.y};
        #pragma unroll
        for (int i = 0; i < 8; i++)
            #pragma unroll
            for (int j = 0; j < 4; j++)
                acc[i][j] = ffma2(pa[i], pb[j], acc[i][j]);
    }

    float* S = g_S[branch] + (size_t)bc * PIX;
    #pragma unroll
    for (int i = 0; i < 8; i++) {
        float* o = S + (i0 + i) * 64 + j0;
        *(float4*)(o)     = make_float4(lo32(acc[i][0]), hi32(acc[i][0]),
                                        lo32(acc[i][1]), hi32(acc[i][1]));
        *(float4*)(o + 4) = make_float4(lo32(acc[i][2]), hi32(acc[i][2]),
                                        lo32(acc[i][3]), hi32(acc[i][3]));
    }
}

// ---------------------------------------------------------------------------
// Kernel C: online softmax statistics over channel dim for both branches.
// One thread per (b, pixel); coalesced strided reads over c.
// ---------------------------------------------------------------------------
__global__ __launch_bounds__(256)
void softmax_stats()
{
    const int p = blockIdx.x * 256 + threadIdx.x;   // 0..4095
    const int b = blockIdx.y;
    const float* __restrict__ s1 = g_S[0] + (size_t)b * CP + p;
    const float* __restrict__ s2 = g_S[1] + (size_t)b * CP + p;

    float m1 = -3.4e38f, z1 = 0.f;
    float m2 = -3.4e38f, z2 = 0.f;
    #pragma unroll 8
    for (int c = 0; c < CH; ++c) {
        float v1 = s1[c * PIX];
        float v2 = s2[c * PIX];
        float nm1 = fmaxf(m1, v1);
        z1 = z1 * __expf(m1 - nm1) + __expf(v1 - nm1);
        m1 = nm1;
        float nm2 = fmaxf(m2, v2);
        z2 = z2 * __expf(m2 - nm2) + __expf(v2 - nm2);
        m2 = nm2;
    }
    g_red[b * PIX + p] = make_float4(m1, z1, m2, z2);
}

// ---------------------------------------------------------------------------
// Kernel D: Att = f1*f2 * exp(2*((s1-m1)+(s2-m2))) / (z1*z2)^2
// ---------------------------------------------------------------------------
__global__ __launch_bounds__(256)
void finalize(float* __restrict__ out)
{
    const int e = blockIdx.x * 256 + threadIdx.x;
    const int b = e >> 21;          // / (CH*PIX)
    const int p = e & (PIX - 1);
    float4 r = g_red[(b << 12) + p];
    float s1 = g_S[0][e];
    float s2 = g_S[1][e];
    float f1 = g_f[0][e];
    float f2 = g_f[1][e];
    float rz = 1.0f / (r.y * r.w);
    float ex = __expf(2.0f * ((s1 - r.x) + (s2 - r.z)));
    out[e] = (f1 * f2) * (ex * rz * rz);
}

// ---------------------------------------------------------------------------
extern "C" void kernel_launch(void* const* d_in, const int* in_sizes, int n_in,
                              void* d_out, int out_size)
{
    const float* opt  = (const float*)d_in[0];
    const float* sar  = (const float*)d_in[1];
    const float* Wopt = (const float*)d_in[2];
    const float* Wsar = (const float*)d_in[3];
    float* out = (float*)d_out;

    cudaFuncSetAttribute(attn_gemm, cudaFuncAttributeMaxDynamicSharedMemorySize,
                         ATTN_SMEM);

    conv_gemm<<<dim3(32, 4, 16), 256>>>(opt, sar, Wopt, Wsar);
    attn_gemm<<<dim3(4096, 1, 1), 128, ATTN_SMEM>>>();
    softmax_stats<<<dim3(16, 8), 256>>>();
    finalize<<<TOT / 256, 256>>>(out);
}

// round 10
// speedup vs baseline: 1.3487x; 1.3487x over previous
#include <cuda_runtime.h>
#include <cstdint>

#define BATCH 8
#define CH    512
#define PIX   4096            // 64*64
#define CP    (CH*PIX)        // 2,097,152
#define TOT   (BATCH*CP)      // 16,777,216

// Scratch (device globals: allocation-free per harness rules)
__device__ float  g_f[2][TOT];      // conv outputs f_opt / f_sar
__device__ float  g_S[2][TOT];      // Gram matrices S_opt / S_sar
__device__ float4 g_red[BATCH*PIX]; // per-(b,pixel): (m1, z1, m2, z2)

// ---------------------------------------------------------------------------
// tf32 helpers
// ---------------------------------------------------------------------------
__device__ __forceinline__ float tf32r(float x) {
    uint32_t u; asm("cvt.rna.tf32.f32 %0, %1;" : "=r"(u) : "f"(x));
    return __uint_as_float(u);
}
// m16n8k8 tf32 mma (sm_80 baseline PTX -> HMMA; legal on plain sm_103)
__device__ __forceinline__ void mma1688(float* c, const uint32_t* a, const uint32_t* b) {
    asm volatile(
        "mma.sync.aligned.m16n8k8.row.col.f32.tf32.tf32.f32 "
        "{%0,%1,%2,%3}, {%4,%5,%6,%7}, {%8,%9}, {%0,%1,%2,%3};"
        : "+f"(c[0]), "+f"(c[1]), "+f"(c[2]), "+f"(c[3])
        : "r"(a[0]), "r"(a[1]), "r"(a[2]), "r"(a[3]), "r"(b[0]), "r"(b[1]));
}

// ---------------------------------------------------------------------------
// Kernel A: 1x1 conv as tf32 tensor-core GEMM with 3xTF32 compensation.
// F[o,p] = sum_c W[o,c] X[c,p].  M=512, N=4096, K=512; 16 GEMMs.
// CTA tile 128x128, K slab 16 (two k8 halves), double-buffered smem.
// Smem holds hi/lo split operands in FRAGMENT-MAJOR order:
//   A plane: group (half*8+mtile) stride 132 floats, elem = lane*4 + {0..3}
//   B plane: group (half*16+ntile) stride 66 floats, elem = lane*2 + pair
// so compute-side fragment fetch is one LDS.128 (A) / LDS.64 (B).
// 8 warps, warp tile 64(M)x32(N): 4 mtiles x 4 ntiles, 48 mma per k8.
// ---------------------------------------------------------------------------
#define APLANE 2112                 // 16 groups * 132 floats
#define BPLANE 2112                 // 32 groups * 66 floats
#define SLABF  (2*APLANE + 2*BPLANE)  // 8448 floats per buffer
#define CONV_SMEM (2*SLABF*4)       // 67584 bytes

__global__ __launch_bounds__(256)
void conv_mma(const float* __restrict__ opt, const float* __restrict__ sar,
              const float* __restrict__ Wopt, const float* __restrict__ Wsar)
{
    extern __shared__ float sm[];

    const int t    = threadIdx.x;
    const int w    = t >> 5;
    const int lane = t & 31;
    const int g    = lane >> 2;       // 0..7
    const int tg   = lane & 3;        // 0..3

    const int branch = blockIdx.z >> 3;
    const int batch  = blockIdx.z & 7;
    const float* __restrict__ Wm = branch ? Wsar : Wopt;
    const float* __restrict__ X  = (branch ? sar : opt) + (size_t)batch * CP;
    float* __restrict__ F = g_f[branch] + (size_t)batch * CP;

    const int m_base = blockIdx.y * 128;
    const int n_base = blockIdx.x * 128;

    // ---- staging coordinates ----
    // A: thread t = (mtile 0..7)*32 + lane; loads 4 scalars per k8 half
    const int s_mt = t >> 5;
    const float* Wr1 = Wm + (size_t)(m_base + s_mt * 16 + g) * CH;
    const float* Wr2 = Wr1 + (size_t)8 * CH;
    const int aAdr0 = (0 * 8 + s_mt) * 132 + lane * 4;   // half 0
    const int aAdr1 = (1 * 8 + s_mt) * 132 + lane * 4;   // half 1
    // B: thread reads rows r=t>>4 (16 k-rows), cols (t&15)*8..+7 (one ntile)
    const int brow  = t >> 4;
    const int bntile = t & 15;
    const float* Xp = X + (size_t)brow * PIX + n_base + bntile * 8;
    const int bhalf = brow >> 3, r8 = brow & 7;
    const int bpair = r8 >> 2,  btg = r8 & 3;
    const int bFragBase = (bhalf * 16 + bntile) * 66 + btg * 2 + bpair;

    // ---- compute coordinates ----
    const int wm = w >> 2;            // 0..1  (64-row half)
    const int wn = w & 3;             // 0..3  (32-col strip)

    float acc[4][4][4];
    #pragma unroll
    for (int i = 0; i < 4; i++)
        #pragma unroll
        for (int j = 0; j < 4; j++)
            #pragma unroll
            for (int q = 0; q < 4; q++) acc[i][j][q] = 0.f;

    float  aR[2][4];
    float4 bR[2];

    // slab load (global -> regs)
    auto ldSlab = [&](int k0) {
        #pragma unroll
        for (int h = 0; h < 2; h++) {
            const int kb = k0 + h * 8;
            aR[h][0] = Wr1[kb + tg];
            aR[h][1] = Wr2[kb + tg];
            aR[h][2] = Wr1[kb + tg + 4];
            aR[h][3] = Wr2[kb + tg + 4];
        }
        bR[0] = *(const float4*)(Xp + (size_t)k0 * PIX);
        bR[1] = *(const float4*)(Xp + (size_t)k0 * PIX + 4);
    };
    // slab stage (regs -> smem, hi/lo split, fragment-major)
    auto stage = [&](int buf) {
        float* base = sm + buf * SLABF;
        float* aHi = base;
        float* aLo = base + APLANE;
        float* bHi = base + 2 * APLANE;
        float* bLo = base + 2 * APLANE + BPLANE;
        #pragma unroll
        for (int h = 0; h < 2; h++) {
            float hi[4], lo[4];
            #pragma unroll
            for (int q = 0; q < 4; q++) {
                hi[q] = tf32r(aR[h][q]);
                lo[q] = tf32r(aR[h][q] - hi[q]);
            }
            const int adr = h ? aAdr1 : aAdr0;
            *(float4*)&aHi[adr] = make_float4(hi[0], hi[1], hi[2], hi[3]);
            *(float4*)&aLo[adr] = make_float4(lo[0], lo[1], lo[2], lo[3]);
        }
        float bv[8] = {bR[0].x, bR[0].y, bR[0].z, bR[0].w,
                       bR[1].x, bR[1].y, bR[1].z, bR[1].w};
        #pragma unroll
        for (int j = 0; j < 8; j++) {
            float hi = tf32r(bv[j]);
            float lo = tf32r(bv[j] - hi);
            bHi[bFragBase + j * 8] = hi;
            bLo[bFragBase + j * 8] = lo;
        }
    };
    // compute one slab (two k8 halves)
    auto compute = [&](int buf) {
        const float* base = sm + buf * SLABF;
        #pragma unroll
        for (int h = 0; h < 2; h++) {
            uint32_t aH[4][4], aL[4][4], bH[4][2], bL[4][2];
            #pragma unroll
            for (int i = 0; i < 4; i++) {
                const int adr = (h * 8 + wm * 4 + i) * 132 + lane * 4;
                *(uint4*)aH[i] = *(const uint4*)&base[adr];
                *(uint4*)aL[i] = *(const uint4*)&base[APLANE + adr];
            }
            #pragma unroll
            for (int j = 0; j < 4; j++) {
                const int adr = (h * 16 + wn * 4 + j) * 66 + lane * 2;
                *(uint2*)bH[j] = *(const uint2*)&base[2 * APLANE + adr];
                *(uint2*)bL[j] = *(const uint2*)&base[2 * APLANE + BPLANE + adr];
            }
            #pragma unroll
            for (int i = 0; i < 4; i++)
                #pragma unroll
                for (int j = 0; j < 4; j++) {
                    mma1688(acc[i][j], aH[i], bH[j]);
                    mma1688(acc[i][j], aH[i], bL[j]);
                    mma1688(acc[i][j], aL[i], bH[j]);
                }
        }
    };

    ldSlab(0);
    stage(0);
    __syncthreads();

    for (int it = 0; it < 32; ++it) {
        const int buf = it & 1;
        if (it < 31) ldSlab((it + 1) * 16);
        compute(buf);
        if (it < 31) {
            stage(buf ^ 1);
            __syncthreads();
        }
    }

    // epilogue: C frag (c0,c1)=row g cols 2tg,2tg+1; (c2,c3)=row g+8
    #pragma unroll
    for (int i = 0; i < 4; i++) {
        const int row0 = m_base + wm * 64 + i * 16 + g;
        #pragma unroll
        for (int j = 0; j < 4; j++) {
            const int col = n_base + wn * 32 + j * 8 + 2 * tg;
            *(float2*)&F[(size_t)row0 * PIX + col] =
                make_float2(acc[i][j][0], acc[i][j][1]);
            *(float2*)&F[(size_t)(row0 + 8) * PIX + col] =
                make_float2(acc[i][j][2], acc[i][j][3]);
        }
    }
}

// ---------------------------------------------------------------------------
// Kernel B: per-(b,c) Gram matrix S = f^T f (64x64x64), both branches per CTA.
// (R3 version — known good at 948us config.)
// ---------------------------------------------------------------------------
__global__ __launch_bounds__(128)
void attn_gemm()
{
    const int bc = blockIdx.x;                   // 0..4095 = b*512+c
    __shared__ float sh[2][64][64];

    const int t = threadIdx.x;
    {
        const float4* g0 = (const float4*)(g_f[0] + (size_t)bc * PIX);
        const float4* g1 = (const float4*)(g_f[1] + (size_t)bc * PIX);
        float4* s0 = (float4*)&sh[0][0][0];
        float4* s1 = (float4*)&sh[1][0][0];
        #pragma unroll
        for (int i = 0; i < 8; i++) {
            s0[t + 128 * i] = g0[t + 128 * i];
            s1[t + 128 * i] = g1[t + 128 * i];
        }
    }
    __syncthreads();

    const int branch = t >> 6;
    const int tt = t & 63;
    const int i0 = (tt >> 3) * 8;
    const int j0 = (tt & 7) * 8;

    float acc[8][8];
    #pragma unroll
    for (int i = 0; i < 8; i++)
        #pragma unroll
        for (int j = 0; j < 8; j++) acc[i][j] = 0.f;

    for (int h = 0; h < 64; ++h) {
        float4 a0 = *(const float4*)&sh[branch][h][i0];
        float4 a1 = *(const float4*)&sh[branch][h][i0 + 4];
        float4 b0 = *(const float4*)&sh[branch][h][j0];
        float4 b1 = *(const float4*)&sh[branch][h][j0 + 4];
        float ra[8] = {a0.x, a0.y, a0.z, a0.w, a1.x, a1.y, a1.z, a1.w};
        float rb[8] = {b0.x, b0.y, b0.z, b0.w, b1.x, b1.y, b1.z, b1.w};
        #pragma unroll
        for (int i = 0; i < 8; i++)
            #pragma unroll
            for (int j = 0; j < 8; j++)
                acc[i][j] = fmaf(ra[i], rb[j], acc[i][j]);
    }

    float* S = g_S[branch] + (size_t)bc * PIX;
    #pragma unroll
    for (int i = 0; i < 8; i++) {
        float* o = S + (i0 + i) * 64 + j0;
        *(float4*)(o)     = make_float4(acc[i][0], acc[i][1], acc[i][2], acc[i][3]);
        *(float4*)(o + 4) = make_float4(acc[i][4], acc[i][5], acc[i][6], acc[i][7]);
    }
}

// ---------------------------------------------------------------------------
// Kernel C: online softmax statistics over channel dim for both branches.
// ---------------------------------------------------------------------------
__global__ __launch_bounds__(256)
void softmax_stats()
{
    const int p = blockIdx.x * 256 + threadIdx.x;   // 0..4095
    const int b = blockIdx.y;
    const float* __restrict__ s1 = g_S[0] + (size_t)b * CP + p;
    const float* __restrict__ s2 = g_S[1] + (size_t)b * CP + p;

    float m1 = -3.4e38f, z1 = 0.f;
    float m2 = -3.4e38f, z2 = 0.f;
    #pragma unroll 8
    for (int c = 0; c < CH; ++c) {
        float v1 = s1[c * PIX];
        float v2 = s2[c * PIX];
        float nm1 = fmaxf(m1, v1);
        z1 = z1 * __expf(m1 - nm1) + __expf(v1 - nm1);
        m1 = nm1;
        float nm2 = fmaxf(m2, v2);
        z2 = z2 * __expf(m2 - nm2) + __expf(v2 - nm2);
        m2 = nm2;
    }
    g_red[b * PIX + p] = make_float4(m1, z1, m2, z2);
}

// ---------------------------------------------------------------------------
// Kernel D: Att = f1*f2 * exp(2*((s1-m1)+(s2-m2))) / (z1*z2)^2
// ---------------------------------------------------------------------------
__global__ __launch_bounds__(256)
void finalize(float* __restrict__ out)
{
    const int e = blockIdx.x * 256 + threadIdx.x;
    const int b = e >> 21;          // / (CH*PIX)
    const int p = e & (PIX - 1);
    float4 r = g_red[(b << 12) + p];
    float s1 = g_S[0][e];
    float s2 = g_S[1][e];
    float f1 = g_f[0][e];
    float f2 = g_f[1][e];
    float rz = 1.0f / (r.y * r.w);
    float ex = __expf(2.0f * ((s1 - r.x) + (s2 - r.z)));
    out[e] = (f1 * f2) * (ex * rz * rz);
}

// ---------------------------------------------------------------------------
extern "C" void kernel_launch(void* const* d_in, const int* in_sizes, int n_in,
                              void* d_out, int out_size)
{
    const float* opt  = (const float*)d_in[0];
    const float* sar  = (const float*)d_in[1];
    const float* Wopt = (const float*)d_in[2];
    const float* Wsar = (const float*)d_in[3];
    float* out = (float*)d_out;

    cudaFuncSetAttribute(conv_mma, cudaFuncAttributeMaxDynamicSharedMemorySize,
                         CONV_SMEM);

    conv_mma<<<dim3(32, 4, 16), 256, CONV_SMEM>>>(opt, sar, Wopt, Wsar);
    attn_gemm<<<dim3(4096, 1, 1), 128>>>();
    softmax_stats<<<dim3(16, 8), 256>>>();
    finalize<<<TOT / 256, 256>>>(out);
}